// round 13
// baseline (speedup 1.0000x reference)
#include <cuda_runtime.h>

// Problem constants (fixed shapes per reference)
#define B_SZ 1024
#define V_SZ 1024
#define L_SZ 16
#define W_SZ 8192
#define NUM_LEAVES (2 * V_SZ)              // 2048
#define N_INTERNAL (L_SZ * W_SZ)           // 131072
#define TOTAL_NODES (NUM_LEAVES + N_INTERNAL)

#define NBLK 16
#define NTHR 64    // NBLK * NTHR == B_SZ; measured-best grid shape

// Persistent scratch for the general fallback path (__device__ globals,
// zero-initialized at load; g_mark is self-cleaned -> deterministic replays).
__device__ int   g_mark[N_INTERNAL];
__device__ int   g_mlist[L_SZ][W_SZ];
__device__ int4  g_work[L_SZ][W_SZ];
__device__ float g_vals[(size_t)N_INTERNAL * B_SZ];

__device__ __forceinline__ float leafval(const float* __restrict__ x, int node, int b) {
    // node < NUM_LEAVES guaranteed by caller
    const int   v   = node & (V_SZ - 1);               // node or node-V (V is pow2)
    const float raw = __ldg(&x[(size_t)b * V_SZ + v]);
    return (node < V_SZ) ? raw : 1.0f - raw;
}

__device__ __forceinline__ float getval(const float* __restrict__ x, int node, int b) {
    if (node < NUM_LEAVES) return leafval(x, node, b);
    return g_vals[(size_t)(node - NUM_LEAVES) * B_SZ + b];
}

// ---------------------------------------------------------------------------
// Cold general path: full backward-reachability + forward eval, run by one
// block. __noinline__ keeps its (heavy) register allocation out of the hot
// entry path.
// ---------------------------------------------------------------------------
__device__ __noinline__ void general_fallback(const float* __restrict__ x,
                                              const int* __restrict__ left,
                                              const int* __restrict__ right,
                                              const int* __restrict__ op,
                                              float* __restrict__ out) {
    __shared__ int s_cnt[L_SZ];
    const int tid = threadIdx.x;

    if (tid < L_SZ) s_cnt[tid] = (tid == L_SZ - 1) ? 1 : 0;
    if (tid == 0) {
        g_mlist[L_SZ - 1][0] = TOTAL_NODES - 1;
        g_mark[N_INTERNAL - 1] = 1;
    }
    __syncthreads();

    // Phase 1: mark (descending layers). A node in layer j is only enqueued
    // by layers > j, so its frontier list is final when we reach it.
    for (int l = L_SZ - 1; l >= 0; --l) {
        const int n     = s_cnt[l];
        const int avail = NUM_LEAVES + l * W_SZ;
        for (int s = tid; s < n; s += NTHR) {
            const int node = g_mlist[l][s];
            const int w    = node - avail;
            const int lli  = left [l * W_SZ + w] % avail;
            const int rri  = right[l * W_SZ + w] % avail;
            const int ov   = op   [l * W_SZ + w];
            g_work[l][s] = make_int4(node, lli, rri, ov);
            #pragma unroll
            for (int k = 0; k < 2; ++k) {
                const int c = (k == 0) ? lli : rri;
                if (c >= NUM_LEAVES) {
                    if (atomicExch(&g_mark[c - NUM_LEAVES], 1) == 0) {
                        const int j   = (c - NUM_LEAVES) / W_SZ;
                        const int pos = atomicAdd(&s_cnt[j], 1);
                        g_mlist[j][pos] = c;
                    }
                }
            }
        }
        __syncthreads();
    }

    // Phase 2: forward (ascending layers), batch strided over the block.
    for (int l = 0; l < L_SZ; ++l) {
        const int n = s_cnt[l];
        for (int s = 0; s < n; ++s) {
            const int4 wk = g_work[l][s];
            for (int b = tid; b < B_SZ; b += NTHR) {
                const float a = getval(x, wk.y, b);
                const float c = getval(x, wk.z, b);
                const float r = (wk.w == 1) ? (a + c) : (a * c);
                g_vals[(size_t)(wk.x - NUM_LEAVES) * B_SZ + b] = r;
                if (wk.x == TOTAL_NODES - 1) out[b] = r;
            }
        }
        __syncthreads();
    }

    // Phase 3: self-clean marks (restores all-zero invariant for replays).
    for (int l = 0; l < L_SZ; ++l) {
        const int n = s_cnt[l];
        for (int s = tid; s < n; s += NTHR)
            g_mark[g_mlist[l][s] - NUM_LEAVES] = 0;
    }
}

__global__ void __launch_bounds__(NTHR, 1)
fused_kernel(const float* __restrict__ x,
             const int* __restrict__ left,
             const int* __restrict__ right,
             const int* __restrict__ op,
             float* __restrict__ out) {
    const int gid = blockIdx.x * NTHR + threadIdx.x;   // batch element

    // Root node descriptor — three parallel broadcast loads at kernel entry.
    const int li  = __ldg(&left [L_SZ * W_SZ - 1]);
    const int ri  = __ldg(&right[L_SZ * W_SZ - 1]);
    const int opv = __ldg(&op   [L_SZ * W_SZ - 1]);

    // ---- FAST PATH: both root children are raw leaf indices (always true
    // for this input distribution: indices drawn from [0, NUM_LEAVES), and
    // NUM_LEAVES <= avail at every layer so the reference's mod is identity).
    if (((unsigned)li < (unsigned)NUM_LEAVES) & ((unsigned)ri < (unsigned)NUM_LEAVES)) {
        const float a = leafval(x, li, gid);
        const float c = leafval(x, ri, gid);
        out[gid] = (opv == 1) ? (a + c) : (a * c);
        return;
    }

    // ---- GENERAL FALLBACK (cold; correct for arbitrary index data).
    // Same branch decision in every block -> deterministic.
    if (blockIdx.x != 0) return;
    general_fallback(x, left, right, op, out);
}

extern "C" void kernel_launch(void* const* d_in, const int* in_sizes, int n_in,
                              void* d_out, int out_size) {
    const float* x     = (const float*)d_in[0];
    const int*   left  = (const int*)d_in[1];
    const int*   right = (const int*)d_in[2];
    const int*   op    = (const int*)d_in[3];
    float*       out   = (float*)d_out;
    (void)in_sizes; (void)n_in; (void)out_size;

    fused_kernel<<<NBLK, NTHR>>>(x, left, right, op, out);
}

// round 14
// speedup vs baseline: 1.0558x; 1.0558x over previous
#include <cuda_runtime.h>

// Problem constants (fixed shapes per reference)
#define B_SZ 1024
#define V_SZ 1024
#define L_SZ 16
#define W_SZ 8192
#define NUM_LEAVES (2 * V_SZ)              // 2048
#define N_INTERNAL (L_SZ * W_SZ)           // 131072
#define TOTAL_NODES (NUM_LEAVES + N_INTERNAL)

#define NBLK 16
#define NTHR 64    // NBLK * NTHR == B_SZ; measured-best grid shape

// Persistent scratch for the general fallback path (__device__ globals,
// zero-initialized at load; g_mark is self-cleaned -> deterministic replays).
__device__ int   g_mark[N_INTERNAL];
__device__ int   g_mlist[L_SZ][W_SZ];
__device__ int4  g_work[L_SZ][W_SZ];
__device__ float g_vals[(size_t)N_INTERNAL * B_SZ];

__device__ __forceinline__ float leafval(const float* __restrict__ x, int node, int b) {
    // node < NUM_LEAVES guaranteed by caller
    const int   v   = node & (V_SZ - 1);               // node or node-V (V is pow2)
    const float raw = __ldg(&x[(size_t)b * V_SZ + v]);
    return (node < V_SZ) ? raw : 1.0f - raw;
}

__device__ __forceinline__ float getval(const float* __restrict__ x, int node, int b) {
    if (node < NUM_LEAVES) return leafval(x, node, b);
    return g_vals[(size_t)(node - NUM_LEAVES) * B_SZ + b];
}

// ---------------------------------------------------------------------------
// Cold general path: full backward-reachability + forward eval, run by one
// block. __noinline__ keeps its (heavy) register allocation out of the hot
// entry path.
// ---------------------------------------------------------------------------
__device__ __noinline__ void general_fallback(const float* __restrict__ x,
                                              const int* __restrict__ left,
                                              const int* __restrict__ right,
                                              const int* __restrict__ op,
                                              float* __restrict__ out) {
    __shared__ int s_cnt[L_SZ];
    const int tid = threadIdx.x;

    if (tid < L_SZ) s_cnt[tid] = (tid == L_SZ - 1) ? 1 : 0;
    if (tid == 0) {
        g_mlist[L_SZ - 1][0] = TOTAL_NODES - 1;
        g_mark[N_INTERNAL - 1] = 1;
    }
    __syncthreads();

    // Phase 1: mark (descending layers). A node in layer j is only enqueued
    // by layers > j, so its frontier list is final when we reach it.
    for (int l = L_SZ - 1; l >= 0; --l) {
        const int n     = s_cnt[l];
        const int avail = NUM_LEAVES + l * W_SZ;
        for (int s = tid; s < n; s += NTHR) {
            const int node = g_mlist[l][s];
            const int w    = node - avail;
            const int lli  = left [l * W_SZ + w] % avail;
            const int rri  = right[l * W_SZ + w] % avail;
            const int ov   = op   [l * W_SZ + w];
            g_work[l][s] = make_int4(node, lli, rri, ov);
            #pragma unroll
            for (int k = 0; k < 2; ++k) {
                const int c = (k == 0) ? lli : rri;
                if (c >= NUM_LEAVES) {
                    if (atomicExch(&g_mark[c - NUM_LEAVES], 1) == 0) {
                        const int j   = (c - NUM_LEAVES) / W_SZ;
                        const int pos = atomicAdd(&s_cnt[j], 1);
                        g_mlist[j][pos] = c;
                    }
                }
            }
        }
        __syncthreads();
    }

    // Phase 2: forward (ascending layers), batch strided over the block.
    for (int l = 0; l < L_SZ; ++l) {
        const int n = s_cnt[l];
        for (int s = 0; s < n; ++s) {
            const int4 wk = g_work[l][s];
            for (int b = tid; b < B_SZ; b += NTHR) {
                const float a = getval(x, wk.y, b);
                const float c = getval(x, wk.z, b);
                const float r = (wk.w == 1) ? (a + c) : (a * c);
                g_vals[(size_t)(wk.x - NUM_LEAVES) * B_SZ + b] = r;
                if (wk.x == TOTAL_NODES - 1) out[b] = r;
            }
        }
        __syncthreads();
    }

    // Phase 3: self-clean marks (restores all-zero invariant for replays).
    for (int l = 0; l < L_SZ; ++l) {
        const int n = s_cnt[l];
        for (int s = tid; s < n; s += NTHR)
            g_mark[g_mlist[l][s] - NUM_LEAVES] = 0;
    }
}

__global__ void __launch_bounds__(NTHR, 1)
fused_kernel(const float* __restrict__ x,
             const int* __restrict__ left,
             const int* __restrict__ right,
             const int* __restrict__ op,
             float* __restrict__ out) {
    const int gid = blockIdx.x * NTHR + threadIdx.x;   // batch element

    // Root node descriptor — three parallel broadcast loads at kernel entry.
    const int li  = __ldg(&left [L_SZ * W_SZ - 1]);
    const int ri  = __ldg(&right[L_SZ * W_SZ - 1]);
    const int opv = __ldg(&op   [L_SZ * W_SZ - 1]);

    // ---- FAST PATH: both root children are raw leaf indices (always true
    // for this input distribution: indices drawn from [0, NUM_LEAVES), and
    // NUM_LEAVES <= avail at every layer so the reference's mod is identity).
    if (((unsigned)li < (unsigned)NUM_LEAVES) & ((unsigned)ri < (unsigned)NUM_LEAVES)) {
        const float a = leafval(x, li, gid);
        const float c = leafval(x, ri, gid);
        out[gid] = (opv == 1) ? (a + c) : (a * c);
        return;
    }

    // ---- GENERAL FALLBACK (cold; correct for arbitrary index data).
    // Same branch decision in every block -> deterministic.
    if (blockIdx.x != 0) return;
    general_fallback(x, left, right, op, out);
}

extern "C" void kernel_launch(void* const* d_in, const int* in_sizes, int n_in,
                              void* d_out, int out_size) {
    const float* x     = (const float*)d_in[0];
    const int*   left  = (const int*)d_in[1];
    const int*   right = (const int*)d_in[2];
    const int*   op    = (const int*)d_in[3];
    float*       out   = (float*)d_out;
    (void)in_sizes; (void)n_in; (void)out_size;

    fused_kernel<<<NBLK, NTHR>>>(x, left, right, op, out);
}

// round 15
// speedup vs baseline: 1.4150x; 1.3401x over previous
#include <cuda_runtime.h>

// Problem constants (fixed shapes per reference)
#define B_SZ 1024
#define V_SZ 1024
#define L_SZ 16
#define W_SZ 8192
#define NUM_LEAVES (2 * V_SZ)              // 2048
#define N_INTERNAL (L_SZ * W_SZ)           // 131072
#define TOTAL_NODES (NUM_LEAVES + N_INTERNAL)

#define NBLK 16
#define NTHR 64    // NBLK * NTHR == B_SZ; measured-best grid shape

// Persistent scratch for the general fallback path (__device__ globals,
// zero-initialized at load; g_mark is self-cleaned -> deterministic replays).
__device__ int   g_mark[N_INTERNAL];
__device__ int   g_mlist[L_SZ][W_SZ];
__device__ int4  g_work[L_SZ][W_SZ];
__device__ float g_vals[(size_t)N_INTERNAL * B_SZ];

__device__ __forceinline__ float leafval(const float* __restrict__ x, int node, int b) {
    // node < NUM_LEAVES guaranteed by caller
    const int   v   = node & (V_SZ - 1);               // node or node-V (V is pow2)
    const float raw = __ldg(&x[(size_t)b * V_SZ + v]);
    return (node < V_SZ) ? raw : 1.0f - raw;
}

__device__ __forceinline__ float getval(const float* __restrict__ x, int node, int b) {
    if (node < NUM_LEAVES) return leafval(x, node, b);
    return g_vals[(size_t)(node - NUM_LEAVES) * B_SZ + b];
}

// ---------------------------------------------------------------------------
// Cold general path: full backward-reachability + forward eval, run by one
// block. __noinline__ keeps its (heavy) register allocation out of the hot
// entry path.
// ---------------------------------------------------------------------------
__device__ __noinline__ void general_fallback(const float* __restrict__ x,
                                              const int* __restrict__ left,
                                              const int* __restrict__ right,
                                              const int* __restrict__ op,
                                              float* __restrict__ out) {
    __shared__ int s_cnt[L_SZ];
    const int tid = threadIdx.x;

    if (tid < L_SZ) s_cnt[tid] = (tid == L_SZ - 1) ? 1 : 0;
    if (tid == 0) {
        g_mlist[L_SZ - 1][0] = TOTAL_NODES - 1;
        g_mark[N_INTERNAL - 1] = 1;
    }
    __syncthreads();

    // Phase 1: mark (descending layers). A node in layer j is only enqueued
    // by layers > j, so its frontier list is final when we reach it.
    for (int l = L_SZ - 1; l >= 0; --l) {
        const int n     = s_cnt[l];
        const int avail = NUM_LEAVES + l * W_SZ;
        for (int s = tid; s < n; s += NTHR) {
            const int node = g_mlist[l][s];
            const int w    = node - avail;
            const int lli  = left [l * W_SZ + w] % avail;
            const int rri  = right[l * W_SZ + w] % avail;
            const int ov   = op   [l * W_SZ + w];
            g_work[l][s] = make_int4(node, lli, rri, ov);
            #pragma unroll
            for (int k = 0; k < 2; ++k) {
                const int c = (k == 0) ? lli : rri;
                if (c >= NUM_LEAVES) {
                    if (atomicExch(&g_mark[c - NUM_LEAVES], 1) == 0) {
                        const int j   = (c - NUM_LEAVES) / W_SZ;
                        const int pos = atomicAdd(&s_cnt[j], 1);
                        g_mlist[j][pos] = c;
                    }
                }
            }
        }
        __syncthreads();
    }

    // Phase 2: forward (ascending layers), batch strided over the block.
    for (int l = 0; l < L_SZ; ++l) {
        const int n = s_cnt[l];
        for (int s = 0; s < n; ++s) {
            const int4 wk = g_work[l][s];
            for (int b = tid; b < B_SZ; b += NTHR) {
                const float a = getval(x, wk.y, b);
                const float c = getval(x, wk.z, b);
                const float r = (wk.w == 1) ? (a + c) : (a * c);
                g_vals[(size_t)(wk.x - NUM_LEAVES) * B_SZ + b] = r;
                if (wk.x == TOTAL_NODES - 1) out[b] = r;
            }
        }
        __syncthreads();
    }

    // Phase 3: self-clean marks (restores all-zero invariant for replays).
    for (int l = 0; l < L_SZ; ++l) {
        const int n = s_cnt[l];
        for (int s = tid; s < n; s += NTHR)
            g_mark[g_mlist[l][s] - NUM_LEAVES] = 0;
    }
}

__global__ void __launch_bounds__(NTHR, 1)
fused_kernel(const float* __restrict__ x,
             const int* __restrict__ left,
             const int* __restrict__ right,
             const int* __restrict__ op,
             float* __restrict__ out) {
    const int gid = blockIdx.x * NTHR + threadIdx.x;   // batch element

    // Root node descriptor — three parallel broadcast loads at kernel entry.
    const int li  = __ldg(&left [L_SZ * W_SZ - 1]);
    const int ri  = __ldg(&right[L_SZ * W_SZ - 1]);
    const int opv = __ldg(&op   [L_SZ * W_SZ - 1]);

    // ---- FAST PATH: both root children are raw leaf indices (always true
    // for this input distribution: indices drawn from [0, NUM_LEAVES), and
    // NUM_LEAVES <= avail at every layer so the reference's mod is identity).
    if (((unsigned)li < (unsigned)NUM_LEAVES) & ((unsigned)ri < (unsigned)NUM_LEAVES)) {
        const float a = leafval(x, li, gid);
        const float c = leafval(x, ri, gid);
        out[gid] = (opv == 1) ? (a + c) : (a * c);
        return;
    }

    // ---- GENERAL FALLBACK (cold; correct for arbitrary index data).
    // Same branch decision in every block -> deterministic.
    if (blockIdx.x != 0) return;
    general_fallback(x, left, right, op, out);
}

extern "C" void kernel_launch(void* const* d_in, const int* in_sizes, int n_in,
                              void* d_out, int out_size) {
    const float* x     = (const float*)d_in[0];
    const int*   left  = (const int*)d_in[1];
    const int*   right = (const int*)d_in[2];
    const int*   op    = (const int*)d_in[3];
    float*       out   = (float*)d_out;
    (void)in_sizes; (void)n_in; (void)out_size;

    fused_kernel<<<NBLK, NTHR>>>(x, left, right, op, out);
}

// round 16
// speedup vs baseline: 1.4345x; 1.0138x over previous
#include <cuda_runtime.h>

// Problem constants (fixed shapes per reference)
#define B_SZ 1024
#define V_SZ 1024
#define L_SZ 16
#define W_SZ 8192
#define NUM_LEAVES (2 * V_SZ)              // 2048
#define N_INTERNAL (L_SZ * W_SZ)           // 131072
#define TOTAL_NODES (NUM_LEAVES + N_INTERNAL)

#define NBLK 16
#define NTHR 64    // NBLK * NTHR == B_SZ; measured-best grid shape

// Persistent scratch for the general fallback path (__device__ globals,
// zero-initialized at load; g_mark is self-cleaned -> deterministic replays).
__device__ int   g_mark[N_INTERNAL];
__device__ int   g_mlist[L_SZ][W_SZ];
__device__ int4  g_work[L_SZ][W_SZ];
__device__ float g_vals[(size_t)N_INTERNAL * B_SZ];

__device__ __forceinline__ float leafval(const float* __restrict__ x, int node, int b) {
    // node < NUM_LEAVES guaranteed by caller
    const int   v   = node & (V_SZ - 1);               // node or node-V (V is pow2)
    const float raw = __ldg(&x[(size_t)b * V_SZ + v]);
    return (node < V_SZ) ? raw : 1.0f - raw;
}

__device__ __forceinline__ float getval(const float* __restrict__ x, int node, int b) {
    if (node < NUM_LEAVES) return leafval(x, node, b);
    return g_vals[(size_t)(node - NUM_LEAVES) * B_SZ + b];
}

// ---------------------------------------------------------------------------
// Cold general path: full backward-reachability + forward eval, run by one
// block. __noinline__ keeps its (heavy) register allocation out of the hot
// entry path.
// ---------------------------------------------------------------------------
__device__ __noinline__ void general_fallback(const float* __restrict__ x,
                                              const int* __restrict__ left,
                                              const int* __restrict__ right,
                                              const int* __restrict__ op,
                                              float* __restrict__ out) {
    __shared__ int s_cnt[L_SZ];
    const int tid = threadIdx.x;

    if (tid < L_SZ) s_cnt[tid] = (tid == L_SZ - 1) ? 1 : 0;
    if (tid == 0) {
        g_mlist[L_SZ - 1][0] = TOTAL_NODES - 1;
        g_mark[N_INTERNAL - 1] = 1;
    }
    __syncthreads();

    // Phase 1: mark (descending layers). A node in layer j is only enqueued
    // by layers > j, so its frontier list is final when we reach it.
    for (int l = L_SZ - 1; l >= 0; --l) {
        const int n     = s_cnt[l];
        const int avail = NUM_LEAVES + l * W_SZ;
        for (int s = tid; s < n; s += NTHR) {
            const int node = g_mlist[l][s];
            const int w    = node - avail;
            const int lli  = left [l * W_SZ + w] % avail;
            const int rri  = right[l * W_SZ + w] % avail;
            const int ov   = op   [l * W_SZ + w];
            g_work[l][s] = make_int4(node, lli, rri, ov);
            #pragma unroll
            for (int k = 0; k < 2; ++k) {
                const int c = (k == 0) ? lli : rri;
                if (c >= NUM_LEAVES) {
                    if (atomicExch(&g_mark[c - NUM_LEAVES], 1) == 0) {
                        const int j   = (c - NUM_LEAVES) / W_SZ;
                        const int pos = atomicAdd(&s_cnt[j], 1);
                        g_mlist[j][pos] = c;
                    }
                }
            }
        }
        __syncthreads();
    }

    // Phase 2: forward (ascending layers), batch strided over the block.
    for (int l = 0; l < L_SZ; ++l) {
        const int n = s_cnt[l];
        for (int s = 0; s < n; ++s) {
            const int4 wk = g_work[l][s];
            for (int b = tid; b < B_SZ; b += NTHR) {
                const float a = getval(x, wk.y, b);
                const float c = getval(x, wk.z, b);
                const float r = (wk.w == 1) ? (a + c) : (a * c);
                g_vals[(size_t)(wk.x - NUM_LEAVES) * B_SZ + b] = r;
                if (wk.x == TOTAL_NODES - 1) out[b] = r;
            }
        }
        __syncthreads();
    }

    // Phase 3: self-clean marks (restores all-zero invariant for replays).
    for (int l = 0; l < L_SZ; ++l) {
        const int n = s_cnt[l];
        for (int s = tid; s < n; s += NTHR)
            g_mark[g_mlist[l][s] - NUM_LEAVES] = 0;
    }
}

__global__ void __launch_bounds__(NTHR, 1)
fused_kernel(const float* __restrict__ x,
             const int* __restrict__ left,
             const int* __restrict__ right,
             const int* __restrict__ op,
             float* __restrict__ out) {
    const int gid = blockIdx.x * NTHR + threadIdx.x;   // batch element

    // Root node descriptor — three parallel broadcast loads at kernel entry.
    const int li  = __ldg(&left [L_SZ * W_SZ - 1]);
    const int ri  = __ldg(&right[L_SZ * W_SZ - 1]);
    const int opv = __ldg(&op   [L_SZ * W_SZ - 1]);

    // ---- FAST PATH: both root children are raw leaf indices (always true
    // for this input distribution: indices drawn from [0, NUM_LEAVES), and
    // NUM_LEAVES <= avail at every layer so the reference's mod is identity).
    if (((unsigned)li < (unsigned)NUM_LEAVES) & ((unsigned)ri < (unsigned)NUM_LEAVES)) {
        const float a = leafval(x, li, gid);
        const float c = leafval(x, ri, gid);
        out[gid] = (opv == 1) ? (a + c) : (a * c);
        return;
    }

    // ---- GENERAL FALLBACK (cold; correct for arbitrary index data).
    // Same branch decision in every block -> deterministic.
    if (blockIdx.x != 0) return;
    general_fallback(x, left, right, op, out);
}

extern "C" void kernel_launch(void* const* d_in, const int* in_sizes, int n_in,
                              void* d_out, int out_size) {
    const float* x     = (const float*)d_in[0];
    const int*   left  = (const int*)d_in[1];
    const int*   right = (const int*)d_in[2];
    const int*   op    = (const int*)d_in[3];
    float*       out   = (float*)d_out;
    (void)in_sizes; (void)n_in; (void)out_size;

    fused_kernel<<<NBLK, NTHR>>>(x, left, right, op, out);
}